// round 13
// baseline (speedup 1.0000x reference)
#include <cuda_runtime.h>

// DETRMatcher — FINAL (noise-band variant of the best shape).
//
// The reference's softmax/cdist/argmin machinery is dead code w.r.t. the
// returned tensors: matched_indices and tgt_idx scatter 0 into all-zero
// arrays (=> zeros); out_bbox/tgt_bbox are bitwise copies. With JAX x64
// disabled the concatenated output is float32 (8.1M elements):
//   [0, 1.62M)      : 0.0f           (two int32 zero index tensors)
//   [1.62M, 4.86M)  : outputs_coord  (bitwise copy, 3.24M f32)
//   [4.86M, 8.10M)  : target_boxes   (bitwise copy, 3.24M f32)
//
// Measured floor: ~10.0-10.7us across 7 independent levers (MLP 1/4/8,
// TPB 256/512, strided/chunked/segment-specialized grids, default/streaming
// cache policy, 128b/256b accesses); identical code re-measured ±0.7us
// (R9: 10.02ncu/10.34wall vs R11: 10.72/10.72). 58.3MB irreducible traffic
// at ~5.8 TB/s combined + replay ramp IS the floor. This round: TPB=1024
// (last untried trivial config), flat strided float4, copy branches first.

static constexpr int V_ZERO  = 405000;                 // float4 slots of zeros
static constexpr int V_COORD = 810000;                 // float4 slots per copy
static constexpr int V_TOTAL = V_ZERO + 2 * V_COORD;   // 2,025,000
static constexpr int V_MID   = V_ZERO + V_COORD;       // 1,215,000

static constexpr int TPB = 1024;

__global__ void __launch_bounds__(TPB)
detr_matcher_pack_f32(const float4* __restrict__ coord,
                      const float4* __restrict__ boxes,
                      float4* __restrict__ out)
{
    const int j = blockIdx.x * TPB + threadIdx.x;
    if (j >= V_TOTAL) return;

    float4 v;
    if (j >= V_MID) {                    // boxes copy (40% of elements)
        v = boxes[j - V_MID];
    } else if (j >= V_ZERO) {            // coord copy (40%)
        v = coord[j - V_ZERO];
    } else {                             // zero segment (20%)
        v = make_float4(0.f, 0.f, 0.f, 0.f);
    }
    out[j] = v;
}

extern "C" void kernel_launch(void* const* d_in, const int* in_sizes, int n_in,
                              void* d_out, int out_size)
{
    // metadata order: outputs_class, outputs_coord, target_classes, target_boxes
    const float4* coord = (const float4*)d_in[1];
    const float4* boxes = (const float4*)d_in[3];
    float4* out = (float4*)d_out;

    const int blocks = (V_TOTAL + TPB - 1) / TPB;   // 1978
    detr_matcher_pack_f32<<<blocks, TPB>>>(coord, boxes, out);
}